// round 2
// baseline (speedup 1.0000x reference)
#include <cuda_runtime.h>
#include <stdint.h>

// B=4096 rows, P=8192 cols. out[j] = max(x[j], -c[rank_j]), rank by stable
// ascending argsort of key=x*rho. Positives need no rank (x >= 0 >= -c).
#define ROW_P    8192
#define NBKT     8192          // 13-bit bucket of flipped key bits
#define SLOTS    6144          // negatives per row ~ 4096 +- 45 (1 sigma); 45-sigma headroom
#define NTHREADS 1024

// Dynamic smem layout (bytes):
//   res   f32[8192]     @ 0       : x by j, later final answer by j
//   key   u32[SLOTS]    @ 32768   : flipped key bits, bucket-contiguous
//   idx   u16[SLOTS]    @ 57344   : original column index
//   cnt   u32[NBKT/2]   @ 69632   : packed u16-pair bucket counters / offsets
//   base  u16[NBKT+2]   @ 86016   : exclusive scan of counts; [NBKT] = n_neg
#define OFF_RES   0
#define OFF_KEY   32768
#define OFF_IDX   (OFF_KEY + SLOTS * 4)
#define OFF_CNT   (OFF_IDX + SLOTS * 2)
#define OFF_BASE  (OFF_CNT + (NBKT / 2) * 4)
#define SMEM_BYTES (OFF_BASE + (NBKT + 2) * 2)

extern __shared__ unsigned char smem_raw[];

__global__ __launch_bounds__(NTHREADS, 2)
void qp_rank_kernel(const float* __restrict__ x,
                    const float* __restrict__ rho,
                    const float* __restrict__ c,
                    float* __restrict__ out)
{
    float*    res    = (float*)   (smem_raw + OFF_RES);
    uint32_t* s_key  = (uint32_t*)(smem_raw + OFF_KEY);
    uint16_t* s_idx  = (uint16_t*)(smem_raw + OFF_IDX);
    uint32_t* s_cnt  = (uint32_t*)(smem_raw + OFF_CNT);
    uint16_t* s_base = (uint16_t*)(smem_raw + OFF_BASE);
    __shared__ uint32_t wsum[32];

    const int t   = threadIdx.x;
    const int row = blockIdx.x;
    const float4* __restrict__ x4 = (const float4*)(x   + (size_t)row * ROW_P);
    const float4* __restrict__ r4 = (const float4*)(rho + (size_t)row * ROW_P);
    float4* __restrict__ out4     = (float4*)(out + (size_t)row * ROW_P);
    float4* res4 = (float4*)res;

    // ---- zero packed bucket counters ----
    #pragma unroll
    for (int i = t; i < NBKT / 2; i += NTHREADS) s_cnt[i] = 0;
    __syncthreads();

    // ---- phase 1: stage x into smem (all j), histogram negative keys ----
    #pragma unroll
    for (int k = 0; k < (ROW_P / 4) / NTHREADS; ++k) {
        int q = t + k * NTHREADS;           // float4 index
        float4 xv = x4[q];
        float4 rv = r4[q];
        res4[q] = xv;
        float kf;
        kf = xv.x * rv.x;
        if (kf < 0.0f) { uint32_t b = (~__float_as_uint(kf)) >> 18;
                         atomicAdd(&s_cnt[b >> 1], (b & 1) ? 0x10000u : 1u); }
        kf = xv.y * rv.y;
        if (kf < 0.0f) { uint32_t b = (~__float_as_uint(kf)) >> 18;
                         atomicAdd(&s_cnt[b >> 1], (b & 1) ? 0x10000u : 1u); }
        kf = xv.z * rv.z;
        if (kf < 0.0f) { uint32_t b = (~__float_as_uint(kf)) >> 18;
                         atomicAdd(&s_cnt[b >> 1], (b & 1) ? 0x10000u : 1u); }
        kf = xv.w * rv.w;
        if (kf < 0.0f) { uint32_t b = (~__float_as_uint(kf)) >> 18;
                         atomicAdd(&s_cnt[b >> 1], (b & 1) ? 0x10000u : 1u); }
    }
    __syncthreads();

    // ---- exclusive scan of 8192 u16 counts (8 buckets/thread) ----
    {
        const int lane = t & 31, warp = t >> 5;
        uint32_t w0 = s_cnt[4 * t + 0], w1 = s_cnt[4 * t + 1];
        uint32_t w2 = s_cnt[4 * t + 2], w3 = s_cnt[4 * t + 3];
        uint32_t cc[8] = { w0 & 0xFFFFu, w0 >> 16, w1 & 0xFFFFu, w1 >> 16,
                           w2 & 0xFFFFu, w2 >> 16, w3 & 0xFFFFu, w3 >> 16 };
        uint32_t tsum = 0;
        #pragma unroll
        for (int i = 0; i < 8; ++i) tsum += cc[i];
        uint32_t s = tsum;
        #pragma unroll
        for (int d = 1; d < 32; d <<= 1) {
            uint32_t v = __shfl_up_sync(0xFFFFFFFFu, s, d);
            if (lane >= d) s += v;
        }
        if (lane == 31) wsum[warp] = s;
        __syncthreads();
        if (warp == 0) {
            uint32_t ws = wsum[lane];
            uint32_t sc = ws;
            #pragma unroll
            for (int d = 1; d < 32; d <<= 1) {
                uint32_t v = __shfl_up_sync(0xFFFFFFFFu, sc, d);
                if (lane >= d) sc += v;
            }
            wsum[lane] = sc - ws;           // exclusive warp offsets
        }
        __syncthreads();
        uint32_t ex = wsum[warp] + (s - tsum);
        uint32_t bv[8];
        uint32_t run = ex;
        #pragma unroll
        for (int i = 0; i < 8; ++i) { bv[i] = run; run += cc[i]; }
        #pragma unroll
        for (int i = 0; i < 8; ++i) s_base[8 * t + i] = (uint16_t)bv[i];
        if (t == NTHREADS - 1) s_base[NBKT] = (uint16_t)run;
        // running scatter offsets, packed pairs, overwrite counters in place
        #pragma unroll
        for (int k2 = 0; k2 < 4; ++k2)
            s_cnt[4 * t + k2] = bv[2 * k2] | (bv[2 * k2 + 1] << 16);
    }
    __syncthreads();

    // ---- phase 2: scatter negatives (key,idx) into bucket-contiguous slots.
    //      x comes from smem; only rho is re-read (L2-hot, vectorized). ----
    #pragma unroll
    for (int k = 0; k < (ROW_P / 4) / NTHREADS; ++k) {
        int q = t + k * NTHREADS;
        float4 xv = res4[q];
        float4 rv = r4[q];
        int j0 = 4 * q;
        float kf;
        #define SCAT(comp, jj)                                                  \
            kf = xv.comp * rv.comp;                                             \
            if (kf < 0.0f) {                                                    \
                uint32_t u = ~__float_as_uint(kf);                              \
                uint32_t b = u >> 18;                                           \
                uint32_t old = atomicAdd(&s_cnt[b >> 1],                        \
                                         (b & 1) ? 0x10000u : 1u);              \
                uint32_t pos = (b & 1) ? (old >> 16) : (old & 0xFFFFu);         \
                s_key[pos] = u;                                                 \
                s_idx[pos] = (uint16_t)(jj);                                    \
            }
        SCAT(x, j0 + 0)
        SCAT(y, j0 + 1)
        SCAT(z, j0 + 2)
        SCAT(w, j0 + 3)
        #undef SCAT
    }
    __syncthreads();

    // ---- phase 3: exact stable rank within bucket, update res in smem ----
    const int n = (int)s_base[NBKT];
    for (int p = t; p < n; p += NTHREADS) {
        uint32_t me    = s_key[p];
        uint32_t b     = me >> 18;
        int      lo    = (int)s_base[b];
        int      hi    = (int)s_base[b + 1];
        uint16_t myidx = s_idx[p];
        int rank = lo;
        for (int q = lo; q < hi; ++q) {
            uint32_t kq = s_key[q];
            rank += (kq < me) ? 1 : 0;
            if (kq == me) rank += (s_idx[q] < myidx) ? 1 : 0;  // rare tie path
        }
        int j = (int)myidx;
        float xv = res[j];
        res[j] = fmaxf(xv, -__ldg(&c[rank]));
    }
    __syncthreads();

    // ---- phase 4: coalesced vector writeback ----
    #pragma unroll
    for (int k = 0; k < (ROW_P / 4) / NTHREADS; ++k) {
        int q = t + k * NTHREADS;
        out4[q] = res4[q];
    }
}

extern "C" void kernel_launch(void* const* d_in, const int* in_sizes, int n_in,
                              void* d_out, int out_size)
{
    const float* x   = (const float*)d_in[0];
    const float* rho = (const float*)d_in[1];
    const float* c   = (const float*)d_in[2];
    float* out = (float*)d_out;

    const int B = in_sizes[0] / ROW_P;   // 4096

    cudaFuncSetAttribute(qp_rank_kernel,
                         cudaFuncAttributeMaxDynamicSharedMemorySize, SMEM_BYTES);
    qp_rank_kernel<<<B, NTHREADS, SMEM_BYTES>>>(x, rho, c, out);
}

// round 3
// speedup vs baseline: 1.0861x; 1.0861x over previous
#include <cuda_runtime.h>
#include <stdint.h>

// B=4096 rows, P=8192 cols. out[j] = max(x[j], -c[rank_j]); rank = stable
// ascending argsort position of key=x*rho. rho>0 => sign(key)=sign(x);
// non-negative keys need no rank (x >= 0 >= -c). Negatives: bucket by top
// 15 bits of flipped key bits, exact stable rank within bucket by compare.
#define ROW_P    8192
#define NBKT     16384        // flipped-key >> 17 (top bit always 0)
#define SLOTS    5120         // negatives/row ~ 4096 +- 45 (1 sigma)
#define NTHREADS 1024

// Dynamic smem (bytes):
//   s_u   u32[8192]   @0      : flipped key bits by column j (0 = positive)
//   s_pos u16[8192]   @32768  : within-bucket arrival index by j
//   pack  u32[SLOTS]  @49152  : (u<<15)|j, bucket-contiguous
//   cnt   u16[NBKT]   @69632  : counts -> inclusive bucket ends (u32-packed pairs)
#define OFF_U     0
#define OFF_POS   32768
#define OFF_PACK  49152
#define OFF_CNT   (OFF_PACK + SLOTS * 4)
#define SMEM_BYTES (OFF_CNT + NBKT * 2)

extern __shared__ unsigned char smem_raw[];

__global__ __launch_bounds__(NTHREADS, 2)
void qp_rank_kernel(const float* __restrict__ x,
                    const float* __restrict__ rho,
                    const float* __restrict__ c,
                    float* __restrict__ out)
{
    uint32_t* s_u    = (uint32_t*)(smem_raw + OFF_U);
    uint16_t* s_pos  = (uint16_t*)(smem_raw + OFF_POS);
    uint32_t* s_pack = (uint32_t*)(smem_raw + OFF_PACK);
    uint32_t* s_cnt32= (uint32_t*)(smem_raw + OFF_CNT);
    uint16_t* s_cnt16= (uint16_t*)(smem_raw + OFF_CNT);
    __shared__ uint32_t wsum[32];
    __shared__ uint32_t s_n;

    const int t   = threadIdx.x;
    const int row = blockIdx.x;
    const float* __restrict__ xr = x + (size_t)row * ROW_P;
    const float4* __restrict__ x4 = (const float4*)xr;
    const float4* __restrict__ r4 = (const float4*)(rho + (size_t)row * ROW_P);
    float* __restrict__ outr      = out + (size_t)row * ROW_P;

    // ---- zero bucket counters (16384 u16 = 8192 u32) ----
    {
        uint4* z = (uint4*)s_cnt32;
        #pragma unroll
        for (int i = t; i < (NBKT / 2) / 4; i += NTHREADS)
            z[i] = make_uint4(0, 0, 0, 0);
    }
    __syncthreads();

    // ---- phase 1: classify. Positives -> out immediately. Negatives ->
    //      histogram atomic; RETURNED old count = within-bucket position,
    //      staged in smem so no second atomic is ever needed. ----
    #pragma unroll
    for (int k = 0; k < (ROW_P / 4) / NTHREADS; ++k) {
        int q = t + k * NTHREADS;
        float4 xv = x4[q];
        float4 rv = r4[q];
        int j0 = 4 * q;
        uint32_t uu[4]; uint32_t pp[4];
        float kf; uint32_t u, b, old;
        #define CLS(comp, i)                                                    \
            kf = xv.comp * rv.comp;                                             \
            if (kf < 0.0f) {                                                    \
                u = ~__float_as_uint(kf);                                       \
                b = u >> 17;                                                    \
                old = atomicAdd(&s_cnt32[b >> 1], (b & 1) ? 0x10000u : 1u);     \
                uu[i] = u;                                                      \
                pp[i] = (b & 1) ? (old >> 16) : (old & 0xFFFFu);                \
            } else {                                                            \
                uu[i] = 0u;                                                     \
                pp[i] = 0u;                                                     \
                outr[j0 + i] = xv.comp;                                         \
            }
        CLS(x, 0) CLS(y, 1) CLS(z, 2) CLS(w, 3)
        #undef CLS
        ((uint4*)s_u)[q] = make_uint4(uu[0], uu[1], uu[2], uu[3]);
        ((uint2*)s_pos)[q] = make_uint2(pp[0] | (pp[1] << 16), pp[2] | (pp[3] << 16));
    }
    __syncthreads();

    // ---- scan 16384 u16 counts -> inclusive bucket ends, in place ----
    {
        const int lane = t & 31, warp = t >> 5;
        uint4 wa = ((uint4*)s_cnt32)[2 * t + 0];
        uint4 wb = ((uint4*)s_cnt32)[2 * t + 1];
        uint32_t cc[16] = {
            wa.x & 0xFFFFu, wa.x >> 16, wa.y & 0xFFFFu, wa.y >> 16,
            wa.z & 0xFFFFu, wa.z >> 16, wa.w & 0xFFFFu, wa.w >> 16,
            wb.x & 0xFFFFu, wb.x >> 16, wb.y & 0xFFFFu, wb.y >> 16,
            wb.z & 0xFFFFu, wb.z >> 16, wb.w & 0xFFFFu, wb.w >> 16 };
        uint32_t inc[16];
        uint32_t run = 0;
        #pragma unroll
        for (int i = 0; i < 16; ++i) { run += cc[i]; inc[i] = run; }
        uint32_t tsum = run;
        uint32_t s = tsum;
        #pragma unroll
        for (int d = 1; d < 32; d <<= 1) {
            uint32_t v = __shfl_up_sync(0xFFFFFFFFu, s, d);
            if (lane >= d) s += v;
        }
        if (lane == 31) wsum[warp] = s;
        __syncthreads();
        if (warp == 0) {
            uint32_t ws = wsum[lane];
            uint32_t sc = ws;
            #pragma unroll
            for (int d = 1; d < 32; d <<= 1) {
                uint32_t v = __shfl_up_sync(0xFFFFFFFFu, sc, d);
                if (lane >= d) sc += v;
            }
            wsum[lane] = sc - ws;          // exclusive warp offsets
        }
        __syncthreads();
        uint32_t ex = wsum[warp] + (s - tsum);
        #pragma unroll
        for (int i = 0; i < 16; ++i) inc[i] += ex;
        ((uint4*)s_cnt32)[2 * t + 0] = make_uint4(
            inc[0] | (inc[1] << 16), inc[2] | (inc[3] << 16),
            inc[4] | (inc[5] << 16), inc[6] | (inc[7] << 16));
        ((uint4*)s_cnt32)[2 * t + 1] = make_uint4(
            inc[8] | (inc[9] << 16), inc[10] | (inc[11] << 16),
            inc[12] | (inc[13] << 16), inc[14] | (inc[15] << 16));
        if (t == NTHREADS - 1) s_n = ex + tsum;
    }
    __syncthreads();

    // ---- phase 2: atomic-free scatter. slot = end[b-1] + staged pos. ----
    #pragma unroll
    for (int k = 0; k < (ROW_P / 4) / NTHREADS; ++k) {
        int q = t + k * NTHREADS;
        uint4 uv = ((uint4*)s_u)[q];
        uint2 pv = ((uint2*)s_pos)[q];
        int j0 = 4 * q;
        uint32_t u, b, lo, pos;
        #define SCAT(field, posv, i)                                            \
            u = uv.field;                                                       \
            if (u != 0u) {                                                      \
                b = u >> 17;                                                    \
                lo = b ? (uint32_t)s_cnt16[b - 1] : 0u;                         \
                pos = (posv);                                                   \
                s_pack[lo + pos] = (u << 15) | (uint32_t)(j0 + i);              \
            }
        SCAT(x, pv.x & 0xFFFFu, 0)
        SCAT(y, pv.x >> 16,     1)
        SCAT(z, pv.y & 0xFFFFu, 2)
        SCAT(w, pv.y >> 16,     3)
        #undef SCAT
    }
    __syncthreads();

    // ---- phase 3: exact stable rank within bucket (single u32 compare:
    //      shared top key bits dropped, low 17 key bits + 13 idx bits). ----
    const int n = (int)s_n;
    for (int p = t; p < n; p += NTHREADS) {
        uint32_t me = s_pack[p];
        int      j  = (int)(me & 0x1FFFu);
        uint32_t b  = s_u[j] >> 17;
        int lo = b ? (int)s_cnt16[b - 1] : 0;
        int hi = (int)s_cnt16[b];
        int rank = lo;
        #pragma unroll 4
        for (int qq = lo; qq < hi; ++qq)
            rank += (s_pack[qq] < me) ? 1 : 0;
        outr[j] = fmaxf(__ldg(&xr[j]), -__ldg(&c[rank]));
    }
}

extern "C" void kernel_launch(void* const* d_in, const int* in_sizes, int n_in,
                              void* d_out, int out_size)
{
    const float* x   = (const float*)d_in[0];
    const float* rho = (const float*)d_in[1];
    const float* c   = (const float*)d_in[2];
    float* out = (float*)d_out;

    const int B = in_sizes[0] / ROW_P;   // 4096

    cudaFuncSetAttribute(qp_rank_kernel,
                         cudaFuncAttributeMaxDynamicSharedMemorySize, SMEM_BYTES);
    qp_rank_kernel<<<B, NTHREADS, SMEM_BYTES>>>(x, rho, c, out);
}

// round 4
// speedup vs baseline: 1.4741x; 1.3573x over previous
#include <cuda_runtime.h>
#include <stdint.h>

// B=4096 rows, P=8192 cols. out[j] = max(x[j], -c[rank_j]); rank = stable
// ascending argsort position of key=x*rho. rho>0 => sign(key)=sign(x);
// non-negative keys need no rank (x >= 0 >= -c >= -1). Negatives: bucket by
// top 15 bits of flipped key bits; exact stable rank within bucket.
#define ROW_P    8192
#define NBKT     16384        // flipped-key >> 17 (top bit always 0)
#define SLOTS    5120         // negatives/row ~ 4096 +- 45 (1 sigma)
#define NTHREADS 1024

// Dynamic smem (bytes), total 100 KB -> 2 CTAs/SM:
//   s_u   u32[8192]   @0      : flipped key bits by column j (0 = positive);
//                               REUSED in phase 3/4 as s_res f32 (=-c[rank])
//   s_pos u16[8192]   @32768  : within-bucket arrival index by j
//   pack  u32[SLOTS]  @49152  : (u<<15)|j, bucket-contiguous
//   cnt   u16[NBKT]   @69632  : counts -> inclusive bucket ends
#define OFF_U     0
#define OFF_POS   32768
#define OFF_PACK  49152
#define OFF_CNT   (OFF_PACK + SLOTS * 4)
#define SMEM_BYTES (OFF_CNT + NBKT * 2)

extern __shared__ unsigned char smem_raw[];

__global__ __launch_bounds__(NTHREADS, 2)
void qp_rank_kernel(const float* __restrict__ x,
                    const float* __restrict__ rho,
                    const float* __restrict__ c,
                    float* __restrict__ out)
{
    uint32_t* s_u    = (uint32_t*)(smem_raw + OFF_U);
    float*    s_res  = (float*)   (smem_raw + OFF_U);     // overlay, phase 3+
    uint16_t* s_pos  = (uint16_t*)(smem_raw + OFF_POS);
    uint32_t* s_pack = (uint32_t*)(smem_raw + OFF_PACK);
    uint32_t* s_cnt32= (uint32_t*)(smem_raw + OFF_CNT);
    uint16_t* s_cnt16= (uint16_t*)(smem_raw + OFF_CNT);
    __shared__ uint32_t wsum[32];
    __shared__ uint32_t s_n;

    const int t   = threadIdx.x;
    const int row = blockIdx.x;
    const float4* __restrict__ x4 = (const float4*)(x   + (size_t)row * ROW_P);
    const float4* __restrict__ r4 = (const float4*)(rho + (size_t)row * ROW_P);
    float4* __restrict__ out4     = (float4*)(out + (size_t)row * ROW_P);

    // ---- zero bucket counters (16384 u16 = 2048 uint4) ----
    {
        uint4* z = (uint4*)s_cnt32;
        #pragma unroll
        for (int i = t; i < (NBKT / 2) / 4; i += NTHREADS)
            z[i] = make_uint4(0, 0, 0, 0);
    }
    __syncthreads();

    // ---- phase 1: classify negatives -> histogram atomic; the RETURNED old
    //      count is the within-bucket position, staged so phase 2 needs no
    //      atomic. No gmem stores here. ----
    #pragma unroll
    for (int k = 0; k < (ROW_P / 4) / NTHREADS; ++k) {
        int q = t + k * NTHREADS;
        float4 xv = x4[q];
        float4 rv = r4[q];
        uint32_t uu[4]; uint32_t pp[4];
        float kf; uint32_t u, b, old;
        #define CLS(comp, i)                                                    \
            kf = xv.comp * rv.comp;                                             \
            if (kf < 0.0f) {                                                    \
                u = ~__float_as_uint(kf);                                       \
                b = u >> 17;                                                    \
                old = atomicAdd(&s_cnt32[b >> 1], (b & 1) ? 0x10000u : 1u);     \
                uu[i] = u;                                                      \
                pp[i] = (b & 1) ? (old >> 16) : (old & 0xFFFFu);                \
            } else {                                                            \
                uu[i] = 0u;                                                     \
                pp[i] = 0u;                                                     \
            }
        CLS(x, 0) CLS(y, 1) CLS(z, 2) CLS(w, 3)
        #undef CLS
        ((uint4*)s_u)[q] = make_uint4(uu[0], uu[1], uu[2], uu[3]);
        ((uint2*)s_pos)[q] = make_uint2(pp[0] | (pp[1] << 16), pp[2] | (pp[3] << 16));
    }
    __syncthreads();

    // ---- scan 16384 u16 counts -> inclusive bucket ends, in place ----
    {
        const int lane = t & 31, warp = t >> 5;
        uint4 wa = ((uint4*)s_cnt32)[2 * t + 0];
        uint4 wb = ((uint4*)s_cnt32)[2 * t + 1];
        uint32_t cc[16] = {
            wa.x & 0xFFFFu, wa.x >> 16, wa.y & 0xFFFFu, wa.y >> 16,
            wa.z & 0xFFFFu, wa.z >> 16, wa.w & 0xFFFFu, wa.w >> 16,
            wb.x & 0xFFFFu, wb.x >> 16, wb.y & 0xFFFFu, wb.y >> 16,
            wb.z & 0xFFFFu, wb.z >> 16, wb.w & 0xFFFFu, wb.w >> 16 };
        uint32_t inc[16];
        uint32_t run = 0;
        #pragma unroll
        for (int i = 0; i < 16; ++i) { run += cc[i]; inc[i] = run; }
        uint32_t tsum = run;
        uint32_t s = tsum;
        #pragma unroll
        for (int d = 1; d < 32; d <<= 1) {
            uint32_t v = __shfl_up_sync(0xFFFFFFFFu, s, d);
            if (lane >= d) s += v;
        }
        if (lane == 31) wsum[warp] = s;
        __syncthreads();
        if (warp == 0) {
            uint32_t ws = wsum[lane];
            uint32_t sc = ws;
            #pragma unroll
            for (int d = 1; d < 32; d <<= 1) {
                uint32_t v = __shfl_up_sync(0xFFFFFFFFu, sc, d);
                if (lane >= d) sc += v;
            }
            wsum[lane] = sc - ws;          // exclusive warp offsets
        }
        __syncthreads();
        uint32_t ex = wsum[warp] + (s - tsum);
        #pragma unroll
        for (int i = 0; i < 16; ++i) inc[i] += ex;
        ((uint4*)s_cnt32)[2 * t + 0] = make_uint4(
            inc[0] | (inc[1] << 16), inc[2] | (inc[3] << 16),
            inc[4] | (inc[5] << 16), inc[6] | (inc[7] << 16));
        ((uint4*)s_cnt32)[2 * t + 1] = make_uint4(
            inc[8] | (inc[9] << 16), inc[10] | (inc[11] << 16),
            inc[12] | (inc[13] << 16), inc[14] | (inc[15] << 16));
        if (t == NTHREADS - 1) s_n = ex + tsum;
    }
    __syncthreads();

    // ---- phase 2: atomic-free scatter. slot = end[b-1] + staged pos. ----
    #pragma unroll
    for (int k = 0; k < (ROW_P / 4) / NTHREADS; ++k) {
        int q = t + k * NTHREADS;
        uint4 uv = ((uint4*)s_u)[q];
        uint2 pv = ((uint2*)s_pos)[q];
        int j0 = 4 * q;
        uint32_t u, b, lo, pos;
        #define SCAT(field, posv, i)                                            \
            u = uv.field;                                                       \
            if (u != 0u) {                                                      \
                b = u >> 17;                                                    \
                lo = b ? (uint32_t)s_cnt16[b - 1] : 0u;                         \
                pos = (posv);                                                   \
                s_pack[lo + pos] = (u << 15) | (uint32_t)(j0 + i);              \
            }
        SCAT(x, pv.x & 0xFFFFu, 0)
        SCAT(y, pv.x >> 16,     1)
        SCAT(z, pv.y & 0xFFFFu, 2)
        SCAT(w, pv.y >> 16,     3)
        #undef SCAT
    }
    __syncthreads();

    // ---- phase 3: exact stable rank within bucket (single u32 compare:
    //      shared top key bits dropped, low 17 key bits + 13 idx bits).
    //      Result -c[rank] stored to smem, overlaying s_u in place (each
    //      column j is owned by exactly one slot; read-before-write is
    //      same-thread, same-address). ----
    const int n = (int)s_n;
    for (int p = t; p < n; p += NTHREADS) {
        uint32_t me = s_pack[p];
        int      j  = (int)(me & 0x1FFFu);
        uint32_t b  = s_u[j] >> 17;
        int lo = b ? (int)s_cnt16[b - 1] : 0;
        int hi = (int)s_cnt16[b];
        int rank = lo;
        for (int qq = lo; qq < hi; ++qq)
            rank += (s_pack[qq] < me) ? 1 : 0;
        s_res[j] = -__ldg(&c[rank]);
    }
    __syncthreads();

    // ---- phase 4: fully coalesced epilogue. x re-read is L2-hot. ----
    #pragma unroll
    for (int k = 0; k < (ROW_P / 4) / NTHREADS; ++k) {
        int q = t + k * NTHREADS;
        float4 xv = x4[q];
        float4 rv = ((float4*)s_res)[q];
        float4 o;
        o.x = (xv.x < 0.0f) ? fmaxf(xv.x, rv.x) : xv.x;
        o.y = (xv.y < 0.0f) ? fmaxf(xv.y, rv.y) : xv.y;
        o.z = (xv.z < 0.0f) ? fmaxf(xv.z, rv.z) : xv.z;
        o.w = (xv.w < 0.0f) ? fmaxf(xv.w, rv.w) : xv.w;
        out4[q] = o;
    }
}

extern "C" void kernel_launch(void* const* d_in, const int* in_sizes, int n_in,
                              void* d_out, int out_size)
{
    const float* x   = (const float*)d_in[0];
    const float* rho = (const float*)d_in[1];
    const float* c   = (const float*)d_in[2];
    float* out = (float*)d_out;

    const int B = in_sizes[0] / ROW_P;   // 4096

    cudaFuncSetAttribute(qp_rank_kernel,
                         cudaFuncAttributeMaxDynamicSharedMemorySize, SMEM_BYTES);
    qp_rank_kernel<<<B, NTHREADS, SMEM_BYTES>>>(x, rho, c, out);
}